// round 9
// baseline (speedup 1.0000x reference)
// R9: GEMM rebuilt with TM=16 tile (71% FFMA2 issue density), single-buffer
// smem + register prefetch (R8's double-buffer regressed ~20us). Gather
// softmax reductions converted to warp shuffles. Scan kept from R8 (8us).
#include <cuda_runtime.h>
#include <math.h>
#include <stdint.h>

#define NN 50000       // nodes
#define KD 512         // input feature dim
#define FO 256         // output classes
#define ER 850000      // edges: 800000 random + 50000 self loops

// -------- scratch (device globals; no allocation allowed) --------
__device__ __align__(16) float g_h[(size_t)NN * FO];   // h = x@W (51.2 MB)
__device__ float g_srow[NN];
__device__ float g_scol[NN];
__device__ int   g_cnt[NN];      // per-row degree
__device__ int   g_off[NN];      // CSR row start
__device__ int   g_cur[NN];      // fill cursor
__device__ int   g_ecol[ER];     // CSR: source node of each edge
__device__ float g_eval[ER];     // CSR: attention coefficient e
#define SCAN_B 196               // scan blocks (196*256 = 50176 >= NN)
__device__ int   g_part[SCAN_B]; // per-block partial sums

// ---- packed f32x2 helpers ----
__device__ __forceinline__ uint64_t pack2(float lo, float hi) {
    uint64_t p;
    asm("mov.b64 %0, {%1, %2};" : "=l"(p) : "f"(lo), "f"(hi));
    return p;
}
__device__ __forceinline__ void unpack2(uint64_t p, float &lo, float &hi) {
    asm("mov.b64 {%0, %1}, %2;" : "=f"(lo), "=f"(hi) : "l"(p));
}
__device__ __forceinline__ void fma2(uint64_t &d, uint64_t a, uint64_t b) {
    asm("fma.rn.f32x2 %0, %1, %2, %0;" : "+l"(d) : "l"(a), "l"(b));
}

// ============ K1: SGEMM h = x @ W, fma.rn.f32x2, TM=16 ============
// CTA tile 256(M) x 64(N), BK=16, 256 threads, thread tile 16(M) x 4(N)
// as 8 M-pairs in packed u64 accumulators.
#define BM 256
#define BN 64
#define BK 16
#define AK_STRIDE 258   // floats per k-row (even -> LDS.64 aligned; %32=2 -> STS banks spread)
#define NCHUNK (KD / BK)

__global__ __launch_bounds__(256) void gemm_kernel(const float* __restrict__ x,
                                                   const float* __restrict__ W) {
    __shared__ float Ask[BK * AK_STRIDE];   // k-major: Ask[k][m]  (16.5 KB)
    __shared__ float Bs[BK][BN];            // 4 KB

    const int tid = threadIdx.x;
    const int tx = tid & 15;        // n group (4 cols)
    const int ty = tid >> 4;        // m group (16 rows)
    const int n0 = blockIdx.x * BN;
    const int m0 = blockIdx.y * BM;

    // A load role: 4 iterations of (row = f>>2, c4 = f&3)
    // B load role: one float4
    const int brow = tid >> 4;      // k
    const int bc4  = tid & 15;

    uint64_t acc[8][4];
#pragma unroll
    for (int i = 0; i < 8; i++)
#pragma unroll
        for (int j = 0; j < 4; j++) acc[i][j] = pack2(0.f, 0.f);

    float4 pa[4];      // A prefetch regs
    float4 pb;         // B prefetch reg

    // ---- load chunk 0 into regs ----
#pragma unroll
    for (int it = 0; it < 4; it++) {
        int f   = tid + it * 256;
        int row = f >> 2;
        int c4  = f & 3;
        int gr  = m0 + row;
        pa[it] = (gr < NN) ? *(const float4*)&x[(size_t)gr * KD + c4 * 4]
                           : make_float4(0.f, 0.f, 0.f, 0.f);
    }
    pb = *(const float4*)&W[(size_t)brow * FO + n0 + bc4 * 4];

    for (int c = 0; c < NCHUNK; c++) {
        // ---- store prefetched regs to smem ----
#pragma unroll
        for (int it = 0; it < 4; it++) {
            int f   = tid + it * 256;
            int row = f >> 2;
            int kb  = (f & 3) * 4;
            Ask[(kb + 0) * AK_STRIDE + row] = pa[it].x;
            Ask[(kb + 1) * AK_STRIDE + row] = pa[it].y;
            Ask[(kb + 2) * AK_STRIDE + row] = pa[it].z;
            Ask[(kb + 3) * AK_STRIDE + row] = pa[it].w;
        }
        *(float4*)&Bs[brow][bc4 * 4] = pb;
        __syncthreads();

        // ---- issue gmem loads for chunk c+1 (hidden behind compute) ----
        if (c + 1 < NCHUNK) {
            int k0 = (c + 1) * BK;
#pragma unroll
            for (int it = 0; it < 4; it++) {
                int f   = tid + it * 256;
                int row = f >> 2;
                int c4  = f & 3;
                int gr  = m0 + row;
                pa[it] = (gr < NN) ? *(const float4*)&x[(size_t)gr * KD + k0 + c4 * 4]
                                   : make_float4(0.f, 0.f, 0.f, 0.f);
            }
            pb = *(const float4*)&W[(size_t)(k0 + brow) * FO + n0 + bc4 * 4];
        }

        // ---- compute 16 kk ----
#pragma unroll
        for (int kk = 0; kk < BK; kk++) {
            uint64_t ap[8];
#pragma unroll
            for (int i = 0; i < 8; i++)
                ap[i] = *(const uint64_t*)&Ask[kk * AK_STRIDE + ty * 16 + 2 * i];
            float4 b4 = *(float4*)&Bs[kk][tx * 4];
            uint64_t bd[4] = { pack2(b4.x, b4.x), pack2(b4.y, b4.y),
                               pack2(b4.z, b4.z), pack2(b4.w, b4.w) };
#pragma unroll
            for (int i = 0; i < 8; i++)
#pragma unroll
                for (int j = 0; j < 4; j++)
                    fma2(acc[i][j], ap[i], bd[j]);
        }
        __syncthreads();
    }

    // ---- epilogue ----
#pragma unroll
    for (int i = 0; i < 8; i++) {
        float lo[4], hi[4];
#pragma unroll
        for (int j = 0; j < 4; j++) unpack2(acc[i][j], lo[j], hi[j]);
        int gr0 = m0 + ty * 16 + 2 * i;
        if (gr0 < NN)
            *(float4*)&g_h[(size_t)gr0 * FO + n0 + tx * 4] =
                make_float4(lo[0], lo[1], lo[2], lo[3]);
        if (gr0 + 1 < NN)
            *(float4*)&g_h[(size_t)(gr0 + 1) * FO + n0 + tx * 4] =
                make_float4(hi[0], hi[1], hi[2], hi[3]);
    }
}

// ========= K2: per-node scores + zero degree counters =========
__global__ __launch_bounds__(256) void scores_kernel(const float* __restrict__ a) {
    int n    = blockIdx.x * (blockDim.x >> 5) + (threadIdx.x >> 5);
    int lane = threadIdx.x & 31;
    if (n >= NN) return;
    const float4* h4  = (const float4*)&g_h[(size_t)n * FO];
    const float4* a14 = (const float4*)a;          // a[0:256]
    const float4* a24 = (const float4*)(a + FO);   // a[256:512]
    float s1 = 0.f, s2 = 0.f;
#pragma unroll
    for (int it = 0; it < 2; it++) {
        int idx = lane + it * 32;
        float4 hv = h4[idx];
        float4 va = a14[idx];
        float4 vb = a24[idx];
        s1 += hv.x * va.x + hv.y * va.y + hv.z * va.z + hv.w * va.w;
        s2 += hv.x * vb.x + hv.y * vb.y + hv.z * vb.z + hv.w * vb.w;
    }
#pragma unroll
    for (int off = 16; off; off >>= 1) {
        s1 += __shfl_xor_sync(0xFFFFFFFFu, s1, off);
        s2 += __shfl_xor_sync(0xFFFFFFFFu, s2, off);
    }
    if (lane == 0) {
        g_srow[n] = s1;
        g_scol[n] = s2;
        g_cnt[n]  = 0;
    }
}

// ============ K3: degree histogram ============
__global__ __launch_bounds__(256) void hist_kernel(const int* __restrict__ row) {
    int i = blockIdx.x * blockDim.x + threadIdx.x;
    if (i >= ER) return;
    atomicAdd(&g_cnt[row[i]], 1);
}

// ============ K4a/b/c: 3-pass parallel exclusive scan over g_cnt ============
__global__ __launch_bounds__(256) void scan_reduce() {
    __shared__ int sh[256];
    int t = threadIdx.x;
    int idx = blockIdx.x * 256 + t;
    int v = (idx < NN) ? g_cnt[idx] : 0;
    sh[t] = v;
    __syncthreads();
#pragma unroll
    for (int s = 128; s; s >>= 1) {
        if (t < s) sh[t] += sh[t + s];
        __syncthreads();
    }
    if (t == 0) g_part[blockIdx.x] = sh[0];
}

__global__ __launch_bounds__(256) void scan_partials() {
    __shared__ int sh[256];
    int t = threadIdx.x;
    sh[t] = (t < SCAN_B) ? g_part[t] : 0;
    __syncthreads();
#pragma unroll
    for (int d = 1; d < 256; d <<= 1) {
        int v = (t >= d) ? sh[t - d] : 0;
        __syncthreads();
        sh[t] += v;
        __syncthreads();
    }
    if (t < SCAN_B) g_part[t] = (t > 0) ? sh[t - 1] : 0;   // exclusive
}

__global__ __launch_bounds__(256) void scan_write() {
    __shared__ int sh[256];
    int t = threadIdx.x;
    int idx = blockIdx.x * 256 + t;
    int v = (idx < NN) ? g_cnt[idx] : 0;
    sh[t] = v;
    __syncthreads();
#pragma unroll
    for (int d = 1; d < 256; d <<= 1) {
        int u = (t >= d) ? sh[t - d] : 0;
        __syncthreads();
        sh[t] += u;
        __syncthreads();
    }
    if (idx < NN) {
        int off = g_part[blockIdx.x] + sh[t] - v;   // exclusive = inclusive - self
        g_off[idx] = off;
        g_cur[idx] = off;
    }
}

// ============ K5: per-edge coefficient + CSR fill ============
__global__ __launch_bounds__(256) void edge_kernel(const int* __restrict__ row,
                                                   const int* __restrict__ col) {
    int i = blockIdx.x * blockDim.x + threadIdx.x;
    if (i >= ER) return;
    int r = row[i], c = col[i];
    float z = g_srow[r] + g_scol[c];
    float l = z > 0.f ? z : 0.2f * z;        // leaky_relu, slope 0.2
    float e = expf(-l);
    int pos = atomicAdd(&g_cur[r], 1);
    g_ecol[pos] = c;
    g_eval[pos] = e;
}

// ==== K6: fused gather-reduce + normalize + ELU + log_softmax ====
__device__ __forceinline__ float wred_max(float v) {
#pragma unroll
    for (int o = 16; o; o >>= 1) v = fmaxf(v, __shfl_xor_sync(0xFFFFFFFFu, v, o));
    return v;
}
__device__ __forceinline__ float wred_sum(float v) {
#pragma unroll
    for (int o = 16; o; o >>= 1) v += __shfl_xor_sync(0xFFFFFFFFu, v, o);
    return v;
}

__global__ __launch_bounds__(256) void gather_final(float* __restrict__ out) {
    int n = blockIdx.x;
    int t = threadIdx.x;
    int lane = t & 31;
    int wid  = t >> 5;
    __shared__ float swred[8];

    int start = g_off[n];
    int deg   = g_cnt[n];          // >= 1 (self loop)

    float a0 = 0.f, a1 = 0.f, rs = 0.f;
    int j = 0;
    for (; j + 4 <= deg; j += 4) {
        int   c0 = g_ecol[start + j];
        int   c1 = g_ecol[start + j + 1];
        int   c2 = g_ecol[start + j + 2];
        int   c3 = g_ecol[start + j + 3];
        float e0 = g_eval[start + j];
        float e1 = g_eval[start + j + 1];
        float e2 = g_eval[start + j + 2];
        float e3 = g_eval[start + j + 3];
        float h0 = g_h[(size_t)c0 * FO + t];
        float h1 = g_h[(size_t)c1 * FO + t];
        float h2 = g_h[(size_t)c2 * FO + t];
        float h3 = g_h[(size_t)c3 * FO + t];
        a0 = fmaf(e0, h0, a0);
        a1 = fmaf(e1, h1, a1);
        a0 = fmaf(e2, h2, a0);
        a1 = fmaf(e3, h3, a1);
        rs += (e0 + e1) + (e2 + e3);
    }
    for (; j < deg; j++) {
        int   c0 = g_ecol[start + j];
        float e0 = g_eval[start + j];
        a0 = fmaf(e0, g_h[(size_t)c0 * FO + t], a0);
        rs += e0;
    }

    float v = (a0 + a1) / rs;
    v = v > 0.f ? v : expm1f(v);             // ELU (alpha=1)

    // block max via shuffles
    float m = wred_max(v);
    if (lane == 0) swred[wid] = m;
    __syncthreads();
    if (wid == 0) {
        float mm = (lane < 8) ? swred[lane] : -1e30f;
        mm = wred_max(mm);
        if (lane == 0) swred[0] = mm;
    }
    __syncthreads();
    float mx = swred[0];
    __syncthreads();

    // block sum of exp
    float ex = expf(v - mx);
    float s = wred_sum(ex);
    if (lane == 0) swred[wid] = s;
    __syncthreads();
    if (wid == 0) {
        float ss = (lane < 8) ? swred[lane] : 0.f;
        ss = wred_sum(ss);
        if (lane == 0) swred[0] = ss;
    }
    __syncthreads();
    float lse = logf(swred[0]) + mx;

    out[(size_t)n * FO + t] = v - lse;
}

// ======================= launch =======================
extern "C" void kernel_launch(void* const* d_in, const int* in_sizes, int n_in,
                              void* d_out, int out_size) {
    const float* x  = (const float*)d_in[0];
    const float* W  = (const float*)d_in[1];
    const float* a  = (const float*)d_in[2];
    const int*   ei = (const int*)d_in[3];
    const int*   row = ei;        // edge_index[0]
    const int*   col = ei + ER;   // edge_index[1]
    float* out = (float*)d_out;

    dim3 g1(FO / BN, (NN + BM - 1) / BM);    // N fastest -> x slab reused in L2
    gemm_kernel  <<<g1, 256>>>(x, W);
    scores_kernel<<<(NN + 7) / 8, 256>>>(a);
    hist_kernel  <<<(ER + 255) / 256, 256>>>(row);
    scan_reduce  <<<SCAN_B, 256>>>();
    scan_partials<<<1, 256>>>();
    scan_write   <<<SCAN_B, 256>>>();
    edge_kernel  <<<(ER + 255) / 256, 256>>>(row, col);
    gather_final <<<NN, 256>>>(out);
}